// round 2
// baseline (speedup 1.0000x reference)
#include <cuda_runtime.h>
#include <cstdint>

// Problem constants (match reference_code)
#define USER_NUM 1000000
#define EMBED_DIM 64
#define BATCH 16384

// FM scoring: out[e] = w[u] + w[i] + b + dot(V[u], V[i])
// (since 0.5*sum((Vu+Vi)^2 - Vu^2 - Vi^2) == sum(Vu*Vi))
//
// NOTE: JAX silently downgrades jnp.int64 -> int32 when x64 mode is off
// (the default), so INPUT is int32 on the wire.
//
// 16 lanes per batch element; lane j loads float4 #j of each 64-float row.
// Rows are 256B (64 fp32), so float4 loads are aligned and coalesced
// within each gathered row (4 lanes per 128B sector pair).
__global__ void __launch_bounds__(256) fm_score_kernel(
    const int*   __restrict__ inp,       // [BATCH, 2] int32
    const float* __restrict__ w,         // [USER_NUM + ITEM_NUM]
    const float* __restrict__ b,         // [1]
    const float* __restrict__ V,         // [USER_NUM + ITEM_NUM, 64]
    float*       __restrict__ out)       // [BATCH]
{
    const int gid  = blockIdx.x * blockDim.x + threadIdx.x;
    const int elem = gid >> 4;     // 16 lanes per element
    const int lane = gid & 15;
    if (elem >= BATCH) return;

    // Both indices in one 64-bit load (8-byte aligned: 2 x int32 per row).
    const int2 idx = __ldg(reinterpret_cast<const int2*>(inp) + elem);
    const long long u = (long long)idx.x;
    const long long i = (long long)idx.y + (long long)USER_NUM;

    const float4* __restrict__ Vu = reinterpret_cast<const float4*>(V + u * EMBED_DIM);
    const float4* __restrict__ Vi = reinterpret_cast<const float4*>(V + i * EMBED_DIM);

    // Issue both gathers back-to-back for MLP=2 per thread before any use.
    const float4 a = __ldg(&Vu[lane]);
    const float4 c = __ldg(&Vi[lane]);

    float dot = a.x * c.x + a.y * c.y + a.z * c.z + a.w * c.w;

    // Reduce across the 16-lane group (contiguous within the warp).
    #pragma unroll
    for (int off = 8; off > 0; off >>= 1)
        dot += __shfl_xor_sync(0xffffffffu, dot, off);

    if (lane == 0) {
        const float lin = __ldg(&w[u]) + __ldg(&w[i]) + __ldg(&b[0]);
        out[elem] = lin + dot;
    }
}

extern "C" void kernel_launch(void* const* d_in, const int* in_sizes, int n_in,
                              void* d_out, int out_size)
{
    const int*   inp = (const int*)d_in[0];    // INPUT int32 [BATCH,2]
    const float* w   = (const float*)d_in[1];  // w
    const float* b   = (const float*)d_in[2];  // b
    const float* V   = (const float*)d_in[3];  // V
    float*       out = (float*)d_out;          // [BATCH,1] float32

    const int threads = 256;
    const int total   = BATCH * 16;
    const int blocks  = (total + threads - 1) / threads;
    fm_score_kernel<<<blocks, threads>>>(inp, w, b, V, out);
}